// round 3
// baseline (speedup 1.0000x reference)
#include <cuda_runtime.h>
#include <math.h>

// Problem constants
#define NB 8
#define NK 1024
#define NL 1024
#define ND 1024
#define NO 6
#define NE 128

// Scratch (tiny): everything l-independent
__device__ __align__(16) float g_v [NB*NO*NE];   // squashed vote  [b,o,e]
__device__ __align__(16) float g_Wv[NB*NO*ND];   // W @ v          [b,o,d]
__device__ __align__(16) float g_a [NB*NK*NO];   // logits         [b,k,o]
__device__ __align__(16) float g_p [NB*NK*NO];   // probs          [b,k,o]
__device__ __align__(16) float g_pu[NB*NO*ND];   // p^T @ u        [b,o,d]
__device__ int g_mask_is_u8;                     // mask dtype flag

// ---------------------------------------------------------------------------
// Detect mask dtype. If int32 (LE), bytes at i%4!=0 over the first 256 bytes
// are all zero (values are 0/1). If uint8 0/1 mask, ~half of them are 1.
__global__ void k_detect(const unsigned char* __restrict__ mraw) {
    if (threadIdx.x == 0) {
        int u8 = 0;
        for (int i = 0; i < 256; i++)
            if ((i & 3) != 0 && mraw[i] != 0) u8 = 1;
        g_mask_is_u8 = u8;
    }
}

__device__ __forceinline__ int mask_at(const unsigned char* mraw, size_t idx) {
    if (g_mask_is_u8) return mraw[idx] != 0;
    return ((const int*)mraw)[idx] != 0;
}

// ---------------------------------------------------------------------------
// init: zero g_pu; optionally set g_p = 1/6 (iteration 0 uniform softmax)
// NB*NO*ND == NB*NK*NO == 49152
__global__ void k_init(int set_p) {
    int i = blockIdx.x * blockDim.x + threadIdx.x;
    if (i < NB*NO*ND) {
        g_pu[i] = 0.f;
        if (set_p) g_p[i] = 1.f / 6.f;
    }
}

// ---------------------------------------------------------------------------
// pu[b,o,d] = sum_k p[b,k,o] * u[b,k,d]   (k-split with atomics)
// grid (NB, ND/256, 8), block 256
__global__ void k_pu(const float* __restrict__ u) {
    __shared__ float sp[128 * NO];           // p chunk [kk][o]
    int b  = blockIdx.x;
    int d  = blockIdx.y * 256 + threadIdx.x;
    int kb = blockIdx.z * 128;

    for (int i = threadIdx.x; i < 128 * NO; i += 256)
        sp[i] = g_p[((size_t)b * NK + kb) * NO + i];
    __syncthreads();

    float acc[NO];
#pragma unroll
    for (int o = 0; o < NO; o++) acc[o] = 0.f;

    const float* up = u + ((size_t)b * NK + kb) * ND + d;
#pragma unroll 4
    for (int kk = 0; kk < 128; kk++) {
        float uv = up[(size_t)kk * ND];
#pragma unroll
        for (int o = 0; o < NO; o++) acc[o] += sp[kk * NO + o] * uv;
    }
#pragma unroll
    for (int o = 0; o < NO; o++)
        atomicAdd(&g_pu[((size_t)b * NO + o) * ND + d], acc[o]);
}

// ---------------------------------------------------------------------------
// S[b,o,e] = sum_d pu[b,o,d] * W[o,d,e];  v = squash(S)
// grid (NB*NO), block 128 (thread = e)
__global__ void k_S_v(const float* __restrict__ W) {
    int bo = blockIdx.x;
    int b = bo / NO, o = bo % NO;
    int e = threadIdx.x;

    const float* x  = g_pu + ((size_t)b * NO + o) * ND;
    const float* Wo = W + (size_t)o * ND * NE;

    float s0 = 0.f, s1 = 0.f, s2 = 0.f, s3 = 0.f;
#pragma unroll 4
    for (int d = 0; d < ND; d += 4) {
        s0 += x[d    ] * Wo[(size_t)(d    ) * NE + e];
        s1 += x[d + 1] * Wo[(size_t)(d + 1) * NE + e];
        s2 += x[d + 2] * Wo[(size_t)(d + 2) * NE + e];
        s3 += x[d + 3] * Wo[(size_t)(d + 3) * NE + e];
    }
    float s = (s0 + s1) + (s2 + s3);

    // block-reduce sum(s^2) over 128 threads
    __shared__ float red[4];
    float sq = s * s;
#pragma unroll
    for (int off = 16; off; off >>= 1) sq += __shfl_xor_sync(0xffffffffu, sq, off);
    if ((e & 31) == 0) red[e >> 5] = sq;
    __syncthreads();
    float tot = red[0] + red[1] + red[2] + red[3];

    float f = tot / (1.f + tot) / (sqrtf(tot) + 1e-8f);
    g_v[((size_t)b * NO + o) * NE + e] = f * s;
}

// ---------------------------------------------------------------------------
// Wv[b,o,d] = sum_e W[o,d,e] * v[b,o,e]
// warp per (b,o,d); block 256 = 8 warps; grid NB*NO*ND/8
__global__ void k_Wv(const float* __restrict__ W) {
    int wg   = blockIdx.x * 8 + (threadIdx.x >> 5);
    int lane = threadIdx.x & 31;
    int d  = wg % ND;
    int bo = wg / ND;
    int b = bo / NO, o = bo % NO;

    const float* Wrow = W + ((size_t)o * ND + d) * NE;
    const float* vv   = g_v + ((size_t)b * NO + o) * NE;

    float s = 0.f;
#pragma unroll
    for (int j = 0; j < 4; j++)
        s += Wrow[lane + 32 * j] * vv[lane + 32 * j];
#pragma unroll
    for (int off = 16; off; off >>= 1) s += __shfl_xor_sync(0xffffffffu, s, off);
    if (lane == 0) g_Wv[((size_t)b * NO + o) * ND + d] = s;
}

// ---------------------------------------------------------------------------
// a[b,k,o] (+)= sum_d u[b,k,d] * Wv[b,o,d];  p = masked softmax over o
// grid (NB, NK/64), block 256 = 8 warps, each warp does 8 k's
template <int ACCUM>
__global__ void k_a_p(const float* __restrict__ u,
                      const unsigned char* __restrict__ mraw) {
    __shared__ float sWv[NO * ND];  // 24 KB
    int b  = blockIdx.x;
    int kb = blockIdx.y * 64;

    for (int i = threadIdx.x; i < NO * ND; i += 256)
        sWv[i] = g_Wv[(size_t)b * NO * ND + i];
    __syncthreads();

    int warp = threadIdx.x >> 5, lane = threadIdx.x & 31;

    for (int ki = 0; ki < 8; ki++) {
        int k = kb + warp * 8 + ki;
        const float* urow = u + ((size_t)b * NK + k) * ND;
        float a0 = 0, a1 = 0, a2 = 0, a3 = 0, a4 = 0, a5 = 0;
#pragma unroll 4
        for (int j = 0; j < 32; j++) {
            int d = lane + 32 * j;
            float uv = urow[d];
            a0 += uv * sWv[d];
            a1 += uv * sWv[ND + d];
            a2 += uv * sWv[2 * ND + d];
            a3 += uv * sWv[3 * ND + d];
            a4 += uv * sWv[4 * ND + d];
            a5 += uv * sWv[5 * ND + d];
        }
#pragma unroll
        for (int off = 16; off; off >>= 1) {
            a0 += __shfl_xor_sync(0xffffffffu, a0, off);
            a1 += __shfl_xor_sync(0xffffffffu, a1, off);
            a2 += __shfl_xor_sync(0xffffffffu, a2, off);
            a3 += __shfl_xor_sync(0xffffffffu, a3, off);
            a4 += __shfl_xor_sync(0xffffffffu, a4, off);
            a5 += __shfl_xor_sync(0xffffffffu, a5, off);
        }
        if (lane == 0) {
            float av[NO] = {a0, a1, a2, a3, a4, a5};
            size_t base = ((size_t)b * NK + k) * NO;
            if (ACCUM) {
#pragma unroll
                for (int o = 0; o < NO; o++) av[o] += g_a[base + o];
            }
#pragma unroll
            for (int o = 0; o < NO; o++) g_a[base + o] = av[o];

            float pr[NO];
            if (mask_at(mraw, (size_t)b * NK + k)) {
#pragma unroll
                for (int o = 0; o < NO; o++) pr[o] = 1.f / 6.f;
            } else {
                float m = av[0];
#pragma unroll
                for (int o = 1; o < NO; o++) m = fmaxf(m, av[o]);
                float ssum = 0.f;
#pragma unroll
                for (int o = 0; o < NO; o++) { pr[o] = expf(av[o] - m); ssum += pr[o]; }
                float inv = 1.f / ssum;
#pragma unroll
                for (int o = 0; o < NO; o++) pr[o] *= inv;
            }
#pragma unroll
            for (int o = 0; o < NO; o++) g_p[base + o] = pr[o];
        }
    }
}

// ---------------------------------------------------------------------------
// Broadcast writes. outputs_v[b,l,o,e] = v[b,o,e]; probs[b,l,k,o] = p[b,k,o]
// grid (NB, NL/64), block 256
__global__ void k_out_v(float4* __restrict__ out) {
    __shared__ float4 sv[NO * NE / 4];  // 192
    int b  = blockIdx.x;
    int lb = blockIdx.y * 64;
    const float4* vsrc = (const float4*)(g_v + (size_t)b * NO * NE);
    if (threadIdx.x < 192) sv[threadIdx.x] = vsrc[threadIdx.x];
    __syncthreads();
    for (int idx = threadIdx.x; idx < 64 * 192; idx += 256) {
        int l = idx / 192, c = idx % 192;
        out[((size_t)b * NL + lb + l) * 192 + c] = sv[c];
    }
}

// grid (NB, NL/16), block 256
__global__ void k_out_p(float4* __restrict__ outp) {
    __shared__ float4 spp[NK * NO / 4];  // 1536 float4 = 24 KB
    int b  = blockIdx.x;
    int lb = blockIdx.y * 16;
    const float4* psrc = (const float4*)(g_p + (size_t)b * NK * NO);
    for (int i = threadIdx.x; i < 1536; i += 256) spp[i] = psrc[i];
    __syncthreads();
    for (int l = 0; l < 16; l++) {
        float4* dst = outp + ((size_t)b * NL + lb + l) * 1536;
#pragma unroll 2
        for (int i = threadIdx.x; i < 1536; i += 256) dst[i] = spp[i];
    }
}

// ---------------------------------------------------------------------------
extern "C" void kernel_launch(void* const* d_in, const int* in_sizes, int n_in,
                              void* d_out, int out_size) {
    const float*         u    = (const float*)d_in[0];
    // d_in[1] = context_sequence: unused (result is independent of L content)
    const float*         W    = (const float*)d_in[2];
    const unsigned char* mask = (const unsigned char*)d_in[3];

    float* out   = (float*)d_out;
    float4* outv = (float4*)out;                               // [B,L,O,E]
    float4* outp = (float4*)(out + (size_t)NB * NL * NO * NE); // [B,L,K,O]

    dim3 b256(256);

    k_detect<<<1, 32>>>(mask);

    // iteration 0: p = 1/6 uniform
    k_init<<<192, b256>>>(1);
    k_pu<<<dim3(NB, ND / 256, 8), b256>>>(u);
    k_S_v<<<NB * NO, 128>>>(W);                 // v0
    k_Wv<<<NB * NO * ND / 8, b256>>>(W);        // Wv0
    k_a_p<0><<<dim3(NB, NK / 64), b256>>>(u, mask);   // a=u.Wv0, p1

    // iteration 1
    k_init<<<192, b256>>>(0);
    k_pu<<<dim3(NB, ND / 256, 8), b256>>>(u);
    k_S_v<<<NB * NO, 128>>>(W);                 // v1
    k_Wv<<<NB * NO * ND / 8, b256>>>(W);        // Wv1
    k_a_p<1><<<dim3(NB, NK / 64), b256>>>(u, mask);   // a+=u.Wv1, p2

    // iteration 2 (final): v2 from p2
    k_init<<<192, b256>>>(0);
    k_pu<<<dim3(NB, ND / 256, 8), b256>>>(u);
    k_S_v<<<NB * NO, 128>>>(W);                 // v2 (final outputs_v)

    // broadcast outputs over L
    k_out_v<<<dim3(NB, NL / 64), b256>>>(outv);
    k_out_p<<<dim3(NB, NL / 16), b256>>>(outp);

    (void)in_sizes; (void)n_in; (void)out_size;
}

// round 5
// speedup vs baseline: 1.8345x; 1.8345x over previous
#include <cuda_runtime.h>
#include <math.h>

// Problem constants
#define NB 8
#define NK 1024
#define NL 1024
#define ND 1024
#define NO 6
#define NE 128

// Scratch (tiny): everything l-independent
__device__ __align__(16) float g_v [NB*NO*NE];   // squashed vote  [b,o,e]
__device__ __align__(16) float g_S [NB*NO*NE];   // raw vote sum   [b,o,e]
__device__ __align__(16) float g_Wv[NB*NO*ND];   // W @ v          [b,o,d]
__device__ __align__(16) float g_a [NB*NK*NO];   // logits         [b,k,o]
__device__ __align__(16) float g_p [NB*NK*NO];   // probs          [b,k,o]
__device__ __align__(16) float g_pu[NB*NO*ND];   // p^T @ u        [b,o,d]
__device__ int g_mask_is_u8;                     // mask dtype flag

// ---------------------------------------------------------------------------
// Detect mask dtype. If int32 (LE), bytes at i%4!=0 over the first 256 bytes
// are all zero (values are 0/1). If uint8 0/1 mask, ~half of them are 1.
__global__ void k_detect(const unsigned char* __restrict__ mraw) {
    if (threadIdx.x == 0) {
        int u8 = 0;
        for (int i = 0; i < 256; i++)
            if ((i & 3) != 0 && mraw[i] != 0) u8 = 1;
        g_mask_is_u8 = u8;
    }
}

__device__ __forceinline__ int mask_at(const unsigned char* mraw, size_t idx) {
    if (g_mask_is_u8) return mraw[idx] != 0;
    return ((const int*)mraw)[idx] != 0;
}

// ---------------------------------------------------------------------------
// init: zero g_pu and g_S; optionally set g_p = 1/6 (iteration 0 softmax)
// NB*NO*ND == NB*NK*NO == 49152; NB*NO*NE = 6144
__global__ void k_init(int set_p) {
    int i = blockIdx.x * blockDim.x + threadIdx.x;
    if (i < NB*NO*ND) {
        g_pu[i] = 0.f;
        if (set_p) g_p[i] = 1.f / 6.f;
        if (i < NB*NO*NE) g_S[i] = 0.f;
    }
}

// ---------------------------------------------------------------------------
// pu[b,o,d] = sum_k p[b,k,o] * u[b,k,d]   (k-split with atomics)
// grid (NB, ND/256, 8), block 256
__global__ void k_pu(const float* __restrict__ u) {
    __shared__ float sp[128 * NO];           // p chunk [kk][o]
    int b  = blockIdx.x;
    int d  = blockIdx.y * 256 + threadIdx.x;
    int kb = blockIdx.z * 128;

    for (int i = threadIdx.x; i < 128 * NO; i += 256)
        sp[i] = g_p[((size_t)b * NK + kb) * NO + i];
    __syncthreads();

    float acc[NO];
#pragma unroll
    for (int o = 0; o < NO; o++) acc[o] = 0.f;

    const float* up = u + ((size_t)b * NK + kb) * ND + d;
#pragma unroll 4
    for (int kk = 0; kk < 128; kk++) {
        float uv = up[(size_t)kk * ND];
#pragma unroll
        for (int o = 0; o < NO; o++) acc[o] += sp[kk * NO + o] * uv;
    }
#pragma unroll
    for (int o = 0; o < NO; o++)
        atomicAdd(&g_pu[((size_t)b * NO + o) * ND + d], acc[o]);
}

// ---------------------------------------------------------------------------
// S[b,o,e] += sum_{d in chunk} pu[b,o,d] * W[o,d,e]  for all 8 b at once.
// W tile read ONCE per chunk (shared across batch). grid (NO, ND/32), block 128.
__global__ void k_S(const float* __restrict__ W) {
    __shared__ float spu[NB][32];
    int o  = blockIdx.x;
    int dc = blockIdx.y * 32;
    int e  = threadIdx.x;

    // 128 threads load 256 entries: two per thread
#pragma unroll
    for (int i = threadIdx.x; i < NB * 32; i += 128) {
        int b = i >> 5, dd = i & 31;
        spu[b][dd] = g_pu[((size_t)b * NO + o) * ND + dc + dd];
    }
    __syncthreads();

    float acc[NB];
#pragma unroll
    for (int b = 0; b < NB; b++) acc[b] = 0.f;

    const float* Wo = W + ((size_t)o * ND + dc) * NE + e;
#pragma unroll 8
    for (int dd = 0; dd < 32; dd++) {
        float w = Wo[(size_t)dd * NE];
#pragma unroll
        for (int b = 0; b < NB; b++) acc[b] += spu[b][dd] * w;
    }
#pragma unroll
    for (int b = 0; b < NB; b++)
        atomicAdd(&g_S[((size_t)b * NO + o) * NE + e], acc[b]);
}

// ---------------------------------------------------------------------------
// v = squash(S). grid NB*NO, block 128 (thread = e)
__global__ void k_squash() {
    int bo = blockIdx.x;
    int e  = threadIdx.x;
    float s = g_S[(size_t)bo * NE + e];

    __shared__ float red[4];
    float sq = s * s;
#pragma unroll
    for (int off = 16; off; off >>= 1) sq += __shfl_xor_sync(0xffffffffu, sq, off);
    if ((e & 31) == 0) red[e >> 5] = sq;
    __syncthreads();
    float tot = red[0] + red[1] + red[2] + red[3];

    float f = tot / (1.f + tot) / (sqrtf(tot) + 1e-8f);
    g_v[(size_t)bo * NE + e] = f * s;
}

// ---------------------------------------------------------------------------
// Wv[b,o,d] = sum_e W[o,d,e] * v[b,o,e], all 8 b per warp (W row read once).
// grid (NO, ND/8), block 256 = 8 warps (warp = one d)
__global__ void k_Wv(const float* __restrict__ W) {
    __shared__ float sv[NB][NE];  // 4 KB
    int o = blockIdx.x;
    int d = blockIdx.y * 8 + (threadIdx.x >> 5);
    int lane = threadIdx.x & 31;

    for (int i = threadIdx.x; i < NB * NE; i += 256)
        sv[i >> 7][i & 127] = g_v[((size_t)(i >> 7) * NO + o) * NE + (i & 127)];
    __syncthreads();

    const float* Wrow = W + ((size_t)o * ND + d) * NE;
    float wv[4];
#pragma unroll
    for (int j = 0; j < 4; j++) wv[j] = Wrow[lane + 32 * j];

#pragma unroll
    for (int b = 0; b < NB; b++) {
        float s = 0.f;
#pragma unroll
        for (int j = 0; j < 4; j++) s += wv[j] * sv[b][lane + 32 * j];
#pragma unroll
        for (int off = 16; off; off >>= 1) s += __shfl_xor_sync(0xffffffffu, s, off);
        if (lane == 0) g_Wv[((size_t)b * NO + o) * ND + d] = s;
    }
}

// ---------------------------------------------------------------------------
// a[b,k,o] (+)= sum_d u[b,k,d] * Wv[b,o,d];  p = masked softmax over o
// grid (NB, NK/64), block 256 = 8 warps, each warp does 8 k's
template <int ACCUM>
__global__ void k_a_p(const float* __restrict__ u,
                      const unsigned char* __restrict__ mraw) {
    __shared__ float sWv[NO * ND];  // 24 KB
    int b  = blockIdx.x;
    int kb = blockIdx.y * 64;

    for (int i = threadIdx.x; i < NO * ND; i += 256)
        sWv[i] = g_Wv[(size_t)b * NO * ND + i];
    __syncthreads();

    int warp = threadIdx.x >> 5, lane = threadIdx.x & 31;

    for (int ki = 0; ki < 8; ki++) {
        int k = kb + warp * 8 + ki;
        const float* urow = u + ((size_t)b * NK + k) * ND;
        float a0 = 0, a1 = 0, a2 = 0, a3 = 0, a4 = 0, a5 = 0;
#pragma unroll 4
        for (int j = 0; j < 32; j++) {
            int d = lane + 32 * j;
            float uv = urow[d];
            a0 += uv * sWv[d];
            a1 += uv * sWv[ND + d];
            a2 += uv * sWv[2 * ND + d];
            a3 += uv * sWv[3 * ND + d];
            a4 += uv * sWv[4 * ND + d];
            a5 += uv * sWv[5 * ND + d];
        }
#pragma unroll
        for (int off = 16; off; off >>= 1) {
            a0 += __shfl_xor_sync(0xffffffffu, a0, off);
            a1 += __shfl_xor_sync(0xffffffffu, a1, off);
            a2 += __shfl_xor_sync(0xffffffffu, a2, off);
            a3 += __shfl_xor_sync(0xffffffffu, a3, off);
            a4 += __shfl_xor_sync(0xffffffffu, a4, off);
            a5 += __shfl_xor_sync(0xffffffffu, a5, off);
        }
        if (lane == 0) {
            float av[NO] = {a0, a1, a2, a3, a4, a5};
            size_t base = ((size_t)b * NK + k) * NO;
            if (ACCUM) {
#pragma unroll
                for (int o = 0; o < NO; o++) av[o] += g_a[base + o];
            }
#pragma unroll
            for (int o = 0; o < NO; o++) g_a[base + o] = av[o];

            float pr[NO];
            if (mask_at(mraw, (size_t)b * NK + k)) {
#pragma unroll
                for (int o = 0; o < NO; o++) pr[o] = 1.f / 6.f;
            } else {
                float m = av[0];
#pragma unroll
                for (int o = 1; o < NO; o++) m = fmaxf(m, av[o]);
                float ssum = 0.f;
#pragma unroll
                for (int o = 0; o < NO; o++) { pr[o] = expf(av[o] - m); ssum += pr[o]; }
                float inv = 1.f / ssum;
#pragma unroll
                for (int o = 0; o < NO; o++) pr[o] *= inv;
            }
#pragma unroll
            for (int o = 0; o < NO; o++) g_p[base + o] = pr[o];
        }
    }
}

// ---------------------------------------------------------------------------
// Broadcast writes. outputs_v[b,l,o,e] = v[b,o,e]; probs[b,l,k,o] = p[b,k,o]
// grid (NB, NL/64), block 256
__global__ void k_out_v(float4* __restrict__ out) {
    __shared__ float4 sv[NO * NE / 4];  // 192
    int b  = blockIdx.x;
    int lb = blockIdx.y * 64;
    const float4* vsrc = (const float4*)(g_v + (size_t)b * NO * NE);
    if (threadIdx.x < 192) sv[threadIdx.x] = vsrc[threadIdx.x];
    __syncthreads();
    for (int idx = threadIdx.x; idx < 64 * 192; idx += 256) {
        int l = idx / 192, c = idx % 192;
        out[((size_t)b * NL + lb + l) * 192 + c] = sv[c];
    }
}

// grid (NB, NL/16), block 256
__global__ void k_out_p(float4* __restrict__ outp) {
    __shared__ float4 spp[NK * NO / 4];  // 1536 float4 = 24 KB
    int b  = blockIdx.x;
    int lb = blockIdx.y * 16;
    const float4* psrc = (const float4*)(g_p + (size_t)b * NK * NO);
    for (int i = threadIdx.x; i < 1536; i += 256) spp[i] = psrc[i];
    __syncthreads();
    for (int l = 0; l < 16; l++) {
        float4* dst = outp + ((size_t)b * NL + lb + l) * 1536;
#pragma unroll 2
        for (int i = threadIdx.x; i < 1536; i += 256) dst[i] = spp[i];
    }
}

// ---------------------------------------------------------------------------
extern "C" void kernel_launch(void* const* d_in, const int* in_sizes, int n_in,
                              void* d_out, int out_size) {
    const float*         u    = (const float*)d_in[0];
    // d_in[1] = context_sequence: unused (result is independent of L content)
    const float*         W    = (const float*)d_in[2];
    const unsigned char* mask = (const unsigned char*)d_in[3];

    float* out   = (float*)d_out;
    float4* outv = (float4*)out;                               // [B,L,O,E]
    float4* outp = (float4*)(out + (size_t)NB * NL * NO * NE); // [B,L,K,O]

    dim3 b256(256);
    dim3 gS(NO, ND / 32);
    dim3 gWv(NO, ND / 8);

    k_detect<<<1, 32>>>(mask);

    // iteration 0: p = 1/6 uniform
    k_init<<<192, b256>>>(1);
    k_pu<<<dim3(NB, ND / 256, 8), b256>>>(u);
    k_S<<<gS, 128>>>(W);
    k_squash<<<NB * NO, 128>>>();               // v0
    k_Wv<<<gWv, b256>>>(W);                     // Wv0
    k_a_p<0><<<dim3(NB, NK / 64), b256>>>(u, mask);   // a=u.Wv0, p1

    // iteration 1
    k_init<<<192, b256>>>(0);
    k_pu<<<dim3(NB, ND / 256, 8), b256>>>(u);
    k_S<<<gS, 128>>>(W);
    k_squash<<<NB * NO, 128>>>();               // v1
    k_Wv<<<gWv, b256>>>(W);                     // Wv1
    k_a_p<1><<<dim3(NB, NK / 64), b256>>>(u, mask);   // a+=u.Wv1, p2

    // iteration 2 (final): v2 from p2
    k_init<<<192, b256>>>(0);
    k_pu<<<dim3(NB, ND / 256, 8), b256>>>(u);
    k_S<<<gS, 128>>>(W);
    k_squash<<<NB * NO, 128>>>();               // v2 (final outputs_v)

    // broadcast outputs over L
    k_out_v<<<dim3(NB, NL / 64), b256>>>(outv);
    k_out_p<<<dim3(NB, NL / 16), b256>>>(outp);

    (void)in_sizes; (void)n_in; (void)out_size;
}

// round 6
// speedup vs baseline: 2.5133x; 1.3700x over previous
#include <cuda_runtime.h>
#include <math.h>

// Problem constants
#define NB 8
#define NK 1024
#define NL 1024
#define ND 1024
#define NO 6
#define NE 128

// Scratch (tiny): everything l-independent
__device__ __align__(16) float g_S [NB*NO*NE];   // raw vote sum   [b,o,e]
__device__ __align__(16) float g_Wv[NB*NO*ND];   // W @ v          [b,o,d]
__device__ __align__(16) float g_a [NB*NK*NO];   // logits         [b,k,o]
__device__ __align__(16) float g_p [NB*NK*NO];   // probs          [b,k,o]
__device__ __align__(16) float g_pu[NB*NO*ND];   // p^T @ u        [b,o,d]
__device__ int g_mask_is_u8;                     // mask dtype flag

// ---------------------------------------------------------------------------
// Prolog: zero g_pu & g_S, detect mask dtype.
// If mask is int32 (LE), bytes at i%4!=0 over the first 256 bytes are all
// zero (values 0/1). If uint8 0/1 mask, ~half of them are nonzero.
__global__ void k_prolog(const unsigned char* __restrict__ mraw) {
    int i = blockIdx.x * 256 + threadIdx.x;
    if (i < NB*NO*ND) g_pu[i] = 0.f;
    if (i < NB*NO*NE) g_S[i]  = 0.f;
    if (blockIdx.x == 0 && threadIdx.x == 0) {
        int u8 = 0;
        for (int j = 0; j < 256; j++)
            if ((j & 3) != 0 && mraw[j] != 0) u8 = 1;
        g_mask_is_u8 = u8;
    }
}

__device__ __forceinline__ int mask_at(const unsigned char* mraw, size_t idx) {
    if (g_mask_is_u8) return mraw[idx] != 0;
    return ((const int*)mraw)[idx] != 0;
}

// ---------------------------------------------------------------------------
// Iteration-0 shortcut: p0 = 1/6 uniformly, so pu0[b,o,d] = (1/6)*sum_k u —
// o-independent. Compute colsum into g_pu[b][o=0][:].
// grid (NB, ND/256, 16), block 256
__global__ void k_colsum(const float* __restrict__ u) {
    int b  = blockIdx.x;
    int d  = blockIdx.y * 256 + threadIdx.x;
    int kb = blockIdx.z * 64;
    const float* up = u + ((size_t)b * NK + kb) * ND + d;
    float acc = 0.f;
#pragma unroll 8
    for (int kk = 0; kk < 64; kk++) acc += up[(size_t)kk * ND];
    atomicAdd(&g_pu[(size_t)b * NO * ND + d], acc);
}

// ---------------------------------------------------------------------------
// pu[b,o,d] = sum_k p[b,k,o] * u[b,k,d]   (k-split with atomics)
// grid (NB, ND/256, 16), block 256
__global__ void k_pu(const float* __restrict__ u) {
    __shared__ float sp[64 * NO];            // p chunk [kk][o]
    int b  = blockIdx.x;
    int d  = blockIdx.y * 256 + threadIdx.x;
    int kb = blockIdx.z * 64;

    for (int i = threadIdx.x; i < 64 * NO; i += 256)
        sp[i] = g_p[((size_t)b * NK + kb) * NO + i];
    __syncthreads();

    float acc[NO];
#pragma unroll
    for (int o = 0; o < NO; o++) acc[o] = 0.f;

    const float* up = u + ((size_t)b * NK + kb) * ND + d;
#pragma unroll 4
    for (int kk = 0; kk < 64; kk++) {
        float uv = up[(size_t)kk * ND];
#pragma unroll
        for (int o = 0; o < NO; o++) acc[o] += sp[kk * NO + o] * uv;
    }
#pragma unroll
    for (int o = 0; o < NO; o++)
        atomicAdd(&g_pu[((size_t)b * NO + o) * ND + d], acc[o]);
}

// ---------------------------------------------------------------------------
// S[b,o,e] += sum_{d in 16-chunk} pu[b,o,d] * W[o,d,e] for all 8 b at once.
// FIRST: read o-independent colsum (o=0 row) scaled by 1/6.
// grid (NO, ND/16), block 128.
template <int FIRST>
__global__ void k_S(const float* __restrict__ W) {
    __shared__ float spu[NB][16];
    int o  = blockIdx.x;
    int dc = blockIdx.y * 16;
    int e  = threadIdx.x;

    {   // 128 threads load exactly 128 entries
        int b = threadIdx.x >> 4, dd = threadIdx.x & 15;
        float v = FIRST ? g_pu[(size_t)b * NO * ND + dc + dd] * (1.f / 6.f)
                        : g_pu[((size_t)b * NO + o) * ND + dc + dd];
        spu[b][dd] = v;
    }
    __syncthreads();

    float acc[NB];
#pragma unroll
    for (int b = 0; b < NB; b++) acc[b] = 0.f;

    const float* Wo = W + ((size_t)o * ND + dc) * NE + e;
#pragma unroll
    for (int dd = 0; dd < 16; dd++) {
        float w = Wo[(size_t)dd * NE];
#pragma unroll
        for (int b = 0; b < NB; b++) acc[b] += spu[b][dd] * w;
    }
#pragma unroll
    for (int b = 0; b < NB; b++)
        atomicAdd(&g_S[((size_t)b * NO + o) * NE + e], acc[b]);
}

// ---------------------------------------------------------------------------
// Fused squash + Wv: v = squash(S) computed in-block (redundantly, cheap),
// then Wv[b,o,d] = sum_e W[o,d,e]*v[b,o,e] for all 8 b (W row read once).
// grid (NO, ND/8), block 256 = 8 warps (warp = one d)
__global__ void k_WvSq(const float* __restrict__ W) {
    __shared__ float sv[NB][NE];   // 4 KB
    __shared__ float sfac[NB];
    int o = blockIdx.x;
    int wid = threadIdx.x >> 5, lane = threadIdx.x & 31;

    for (int i = threadIdx.x; i < NB * NE; i += 256)
        sv[i >> 7][i & 127] = g_S[((size_t)(i >> 7) * NO + o) * NE + (i & 127)];
    __syncthreads();

    // warp w computes squash factor for b=w
    {
        float sq = 0.f;
#pragma unroll
        for (int j = 0; j < 4; j++) {
            float x = sv[wid][lane + 32 * j];
            sq += x * x;
        }
#pragma unroll
        for (int off = 16; off; off >>= 1) sq += __shfl_xor_sync(0xffffffffu, sq, off);
        if (lane == 0) sfac[wid] = sq / (1.f + sq) / (sqrtf(sq) + 1e-8f);
    }
    __syncthreads();
    for (int i = threadIdx.x; i < NB * NE; i += 256)
        sv[i >> 7][i & 127] *= sfac[i >> 7];
    __syncthreads();

    int d = blockIdx.y * 8 + wid;
    const float* Wrow = W + ((size_t)o * ND + d) * NE;
    float wv[4];
#pragma unroll
    for (int j = 0; j < 4; j++) wv[j] = Wrow[lane + 32 * j];

#pragma unroll
    for (int b = 0; b < NB; b++) {
        float s = 0.f;
#pragma unroll
        for (int j = 0; j < 4; j++) s += wv[j] * sv[b][lane + 32 * j];
#pragma unroll
        for (int off = 16; off; off >>= 1) s += __shfl_xor_sync(0xffffffffu, s, off);
        if (lane == 0) g_Wv[((size_t)b * NO + o) * ND + d] = s;
    }
}

// ---------------------------------------------------------------------------
// a[b,k,o] (+)= sum_d u[b,k,d] * Wv[b,o,d];  p = masked softmax over o.
// Also zeroes this block's slice of g_pu/g_S for the NEXT iteration's atomics
// (this kernel never touches them; kernel boundary orders the writes).
// grid (NB, NK/32), block 256 = 8 warps, each warp does 4 k's
template <int ACCUM>
__global__ void k_a_p(const float* __restrict__ u,
                      const unsigned char* __restrict__ mraw) {
    __shared__ float sWv[NO * ND];  // 24 KB
    int b  = blockIdx.x;
    int kb = blockIdx.y * 32;

    // zero next-iter accumulators: 256 blocks -> 192 g_pu + 24 g_S floats each
    {
        int slice = blockIdx.x * 32 + blockIdx.y;   // 0..255
        if (threadIdx.x < 192) g_pu[(size_t)slice * 192 + threadIdx.x] = 0.f;
        else if (threadIdx.x < 192 + 24) g_S[(size_t)slice * 24 + (threadIdx.x - 192)] = 0.f;
    }

    for (int i = threadIdx.x; i < NO * ND; i += 256)
        sWv[i] = g_Wv[(size_t)b * NO * ND + i];
    __syncthreads();

    int warp = threadIdx.x >> 5, lane = threadIdx.x & 31;

    for (int ki = 0; ki < 4; ki++) {
        int k = kb + warp * 4 + ki;
        const float* urow = u + ((size_t)b * NK + k) * ND;
        float a0 = 0, a1 = 0, a2 = 0, a3 = 0, a4 = 0, a5 = 0;
#pragma unroll 4
        for (int j = 0; j < 32; j++) {
            int d = lane + 32 * j;
            float uv = urow[d];
            a0 += uv * sWv[d];
            a1 += uv * sWv[ND + d];
            a2 += uv * sWv[2 * ND + d];
            a3 += uv * sWv[3 * ND + d];
            a4 += uv * sWv[4 * ND + d];
            a5 += uv * sWv[5 * ND + d];
        }
#pragma unroll
        for (int off = 16; off; off >>= 1) {
            a0 += __shfl_xor_sync(0xffffffffu, a0, off);
            a1 += __shfl_xor_sync(0xffffffffu, a1, off);
            a2 += __shfl_xor_sync(0xffffffffu, a2, off);
            a3 += __shfl_xor_sync(0xffffffffu, a3, off);
            a4 += __shfl_xor_sync(0xffffffffu, a4, off);
            a5 += __shfl_xor_sync(0xffffffffu, a5, off);
        }
        if (lane == 0) {
            float av[NO] = {a0, a1, a2, a3, a4, a5};
            size_t base = ((size_t)b * NK + k) * NO;
            if (ACCUM) {
#pragma unroll
                for (int o = 0; o < NO; o++) av[o] += g_a[base + o];
            }
#pragma unroll
            for (int o = 0; o < NO; o++) g_a[base + o] = av[o];

            float pr[NO];
            if (mask_at(mraw, (size_t)b * NK + k)) {
#pragma unroll
                for (int o = 0; o < NO; o++) pr[o] = 1.f / 6.f;
            } else {
                float m = av[0];
#pragma unroll
                for (int o = 1; o < NO; o++) m = fmaxf(m, av[o]);
                float ssum = 0.f;
#pragma unroll
                for (int o = 0; o < NO; o++) { pr[o] = expf(av[o] - m); ssum += pr[o]; }
                float inv = 1.f / ssum;
#pragma unroll
                for (int o = 0; o < NO; o++) pr[o] *= inv;
            }
#pragma unroll
            for (int o = 0; o < NO; o++) g_p[base + o] = pr[o];
        }
    }
}

// ---------------------------------------------------------------------------
// Final: squash(S) fused with the L-broadcast of outputs_v.
// outputs_v[b,l,o,e] = squash(S)[b,o,e].  grid (NB, NL/64), block 256
__global__ void k_out_v(float4* __restrict__ out) {
    __shared__ __align__(16) float sv[NO * NE];  // 768 floats
    __shared__ float sfac[NO];
    int b  = blockIdx.x;
    int lb = blockIdx.y * 64;
    int wid = threadIdx.x >> 5, lane = threadIdx.x & 31;

    for (int i = threadIdx.x; i < NO * NE; i += 256)
        sv[i] = g_S[(size_t)b * NO * NE + i];
    __syncthreads();

    if (wid < NO) {
        float sq = 0.f;
#pragma unroll
        for (int j = 0; j < 4; j++) {
            float x = sv[wid * NE + lane + 32 * j];
            sq += x * x;
        }
#pragma unroll
        for (int off = 16; off; off >>= 1) sq += __shfl_xor_sync(0xffffffffu, sq, off);
        if (lane == 0) sfac[wid] = sq / (1.f + sq) / (sqrtf(sq) + 1e-8f);
    }
    __syncthreads();
    for (int i = threadIdx.x; i < NO * NE; i += 256)
        sv[i] *= sfac[i >> 7];
    __syncthreads();

    const float4* svv = (const float4*)sv;
    for (int idx = threadIdx.x; idx < 64 * 192; idx += 256) {
        int l = idx / 192, c = idx % 192;
        out[((size_t)b * NL + lb + l) * 192 + c] = svv[c];
    }
}

// probs broadcast: probs[b,l,k,o] = p[b,k,o].  grid (NB, NL/16), block 256
__global__ void k_out_p(float4* __restrict__ outp) {
    __shared__ float4 spp[NK * NO / 4];  // 1536 float4 = 24 KB
    int b  = blockIdx.x;
    int lb = blockIdx.y * 16;
    const float4* psrc = (const float4*)(g_p + (size_t)b * NK * NO);
    for (int i = threadIdx.x; i < 1536; i += 256) spp[i] = psrc[i];
    __syncthreads();
    for (int l = 0; l < 16; l++) {
        float4* dst = outp + ((size_t)b * NL + lb + l) * 1536;
#pragma unroll 2
        for (int i = threadIdx.x; i < 1536; i += 256) dst[i] = spp[i];
    }
}

// ---------------------------------------------------------------------------
extern "C" void kernel_launch(void* const* d_in, const int* in_sizes, int n_in,
                              void* d_out, int out_size) {
    const float*         u    = (const float*)d_in[0];
    // d_in[1] = context_sequence: unused (result is independent of L content)
    const float*         W    = (const float*)d_in[2];
    const unsigned char* mask = (const unsigned char*)d_in[3];

    float* out   = (float*)d_out;
    float4* outv = (float4*)out;                               // [B,L,O,E]
    float4* outp = (float4*)(out + (size_t)NB * NL * NO * NE); // [B,L,K,O]

    dim3 b256(256);
    dim3 gCS(NB, ND / 256, 16);
    dim3 gS(NO, ND / 16);
    dim3 gWv(NO, ND / 8);
    dim3 gAP(NB, NK / 32);

    // iteration 0: uniform p -> colsum shortcut
    k_prolog<<<192, b256>>>(mask);
    k_colsum<<<gCS, b256>>>(u);
    k_S<1><<<gS, 128>>>(W);
    k_WvSq<<<gWv, b256>>>(W);                   // v0 -> Wv0
    k_a_p<0><<<gAP, b256>>>(u, mask);           // a=u.Wv0, p1; zero pu/S

    // iteration 1
    k_pu<<<gCS, b256>>>(u);
    k_S<0><<<gS, 128>>>(W);
    k_WvSq<<<gWv, b256>>>(W);                   // v1 -> Wv1
    k_a_p<1><<<gAP, b256>>>(u, mask);           // a+=u.Wv1, p2; zero pu/S

    // iteration 2 (final): v2 from p2
    k_pu<<<gCS, b256>>>(u);
    k_S<0><<<gS, 128>>>(W);

    // outputs: squash fused into v-broadcast; p broadcast
    k_out_v<<<dim3(NB, NL / 64), b256>>>(outv);
    k_out_p<<<dim3(NB, NL / 16), b256>>>(outp);

    (void)in_sizes; (void)n_in; (void)out_size;
}